// round 13
// baseline (speedup 1.0000x reference)
#include <cuda_runtime.h>
#include <cuda_fp16.h>
#include <cstdint>

#define Bc 8
#define Lc 1024
#define Hc 8
#define Ec 64
#define QT 64      /* q-rows per CTA (4 warps x m16) */
#define ST 64
#define SH 72      /* smem row stride in halves */
#define C2 0.18033688f   /* 0.125 * log2(e) */
#define ONE2 0x3C003C00u /* half2(1.0, 1.0) */

__device__ __forceinline__ uint32_t smem_u32(const void* p) {
    return (uint32_t)__cvta_generic_to_shared(p);
}
__device__ __forceinline__ float ex2f(float x) {
    float r; asm("ex2.approx.f32 %0, %1;" : "=f"(r) : "f"(x)); return r;
}
__device__ __forceinline__ uint32_t hex2(uint32_t x) {
    uint32_t r; asm("ex2.approx.f16x2 %0, %1;" : "=r"(r) : "r"(x)); return r;
}
__device__ __forceinline__ uint32_t hmul2u(uint32_t a, uint32_t b) {
    uint32_t r; asm("mul.f16x2 %0, %1, %2;" : "=r"(r) : "r"(a), "r"(b)); return r;
}
__device__ __forceinline__ void ldsm4(uint32_t& r0, uint32_t& r1, uint32_t& r2, uint32_t& r3, uint32_t a) {
    asm volatile("ldmatrix.sync.aligned.m8n8.x4.shared.b16 {%0,%1,%2,%3}, [%4];"
        : "=r"(r0), "=r"(r1), "=r"(r2), "=r"(r3) : "r"(a));
}
__device__ __forceinline__ void ldsm4t(uint32_t& r0, uint32_t& r1, uint32_t& r2, uint32_t& r3, uint32_t a) {
    asm volatile("ldmatrix.sync.aligned.m8n8.x4.trans.shared.b16 {%0,%1,%2,%3}, [%4];"
        : "=r"(r0), "=r"(r1), "=r"(r2), "=r"(r3) : "r"(a));
}
__device__ __forceinline__ void mma16(float* d, const uint32_t* a, uint32_t b0, uint32_t b1) {
    asm volatile("mma.sync.aligned.m16n8k16.row.col.f32.f16.f16.f32 "
        "{%0,%1,%2,%3}, {%4,%5,%6,%7}, {%8,%9}, {%0,%1,%2,%3};"
        : "+f"(d[0]), "+f"(d[1]), "+f"(d[2]), "+f"(d[3])
        : "r"(a[0]), "r"(a[1]), "r"(a[2]), "r"(a[3]), "r"(b0), "r"(b1));
}
__device__ __forceinline__ uint32_t packh2(float x, float y) {
    __half2 h = __floats2half2_rn(x, y);
    return *(uint32_t*)&h;
}

__global__ __launch_bounds__(128, 4) void fftcca_h16v8(
    const float* __restrict__ Q, const float* __restrict__ K,
    const float* __restrict__ V, const float* __restrict__ QD,
    const float* __restrict__ KD, const float* __restrict__ VD,
    const int* __restrict__ histp, float* __restrict__ O)
{
    extern __shared__ __align__(16) char smraw[];
    __half* sq  = (__half*)smraw;                 // [64][72] q_eff
    __half* sKV = sq + QT * SH;                   // [2 stages][K|V][64][72]
    float* sdiag = (float*)(sKV + 4 * ST * SH);   // [64]

    const int hist = __ldg(histp);
    const int b = blockIdx.z, h = blockIdx.y;
    const int jt = (int)(gridDim.x - 1u - blockIdx.x);   // longest tiles first
    const int l0 = jt * QT;
    const int tid = threadIdx.x;
    const int w = tid >> 5, lane = tid & 31, gid = lane >> 2, tig = lane & 3;
    const int g8 = lane >> 3, rl = lane & 7;
    const uint32_t c2x2 = packh2(C2, C2);
    const int bh64 = ((b * Lc) * Hc + h) << 6;

    // ---- stage Q (row-select Q vs QD, cvt fp16): 64x64 halves = 1024 uint2 ----
    #pragma unroll
    for (int i = 0; i < 8; ++i) {
        int gi = tid + 128 * i;
        int r = gi >> 4, c4 = (gi & 15) << 2;
        int l = l0 + r;
        const float* src = (l < hist) ? Q : QD;
        float4 v = *(const float4*)(src + bh64 + (l << 9) + c4);
        uint2 pk; pk.x = packh2(v.x, v.y); pk.y = packh2(v.z, v.w);
        *(uint2*)(sq + r * SH + c4) = pk;
    }

    // ---- raw diagonal scores (fp32 from global, 2 threads/row) ----
    {
        int r = tid >> 1, part = tid & 1;
        int l = l0 + r;
        float s = 0.f;
        if (l >= hist) {
            int base = bh64 + (l << 9);
            const float* qr = QD + base + part * 32;
            const float* kr = KD + base + part * 32;
            #pragma unroll
            for (int e = 0; e < 32; e += 4) {
                float4 q4 = *(const float4*)(qr + e);
                float4 k4 = *(const float4*)(kr + e);
                s += q4.x * k4.x + q4.y * k4.y + q4.z * k4.z + q4.w * k4.w;
            }
        }
        s += __shfl_xor_sync(0xffffffffu, s, 1);
        if (part == 0) sdiag[r] = s;
    }
    __syncthreads();

    // ---- preload Q A-fragments (tile-invariant) ----
    uint32_t qa[4][4];
    #pragma unroll
    for (int kb = 0; kb < 4; ++kb) {
        int row = w * 16 + (g8 & 1) * 8 + rl;
        int col = kb * 16 + (g8 >> 1) * 8;
        ldsm4(qa[kb][0], qa[kb][1], qa[kb][2], qa[kb][3], smem_u32(sq + row * SH + col));
    }

    /* acc[0..7]: output dims; acc[8]: ones-column row sums */
    float acc[9][4];
    #pragma unroll
    for (int nb = 0; nb < 9; ++nb)
        #pragma unroll
        for (int q = 0; q < 4; ++q) acc[nb][q] = 0.f;

    const int ntiles = jt + 1;      /* diagonal tile is t = jt (all warps active every tile) */

    // ---- stage tile 0 into buffer 0: 64 rows x 8 chunks = 512 chunks ----
    #pragma unroll
    for (int arr = 0; arr < 2; ++arr) {
        const float* src = arr ? V : K;
        __half* dst = sKV + arr * (ST * SH);
        #pragma unroll
        for (int i = 0; i < 4; ++i) {
            int ch = tid + 128 * i;
            int row = ch >> 3, cc = ch & 7;
            const float* g = src + bh64 + (row << 9) + cc * 8;
            float4 a = *(const float4*)g;
            float4 c = *(const float4*)(g + 4);
            uint4 pk;
            pk.x = packh2(a.x, a.y); pk.y = packh2(a.z, a.w);
            pk.z = packh2(c.x, c.y); pk.w = packh2(c.z, c.w);
            *(uint4*)(dst + row * SH + cc * 8) = pk;
        }
    }
    __syncthreads();

    for (int t = 0; t < ntiles; ++t) {
        const int s0 = t * ST;
        const int cur = t & 1;
        const __half* sK = sKV + cur * (2 * ST * SH);
        const __half* sV = sK + ST * SH;

        // ---- stage tile t+1 into the other buffer ----
        if (t + 1 < ntiles) {
            __half* dB = sKV + (cur ^ 1) * (2 * ST * SH);
            #pragma unroll
            for (int arr = 0; arr < 2; ++arr) {
                const float* src = arr ? V : K;
                __half* dst = dB + arr * (ST * SH);
                #pragma unroll
                for (int i = 0; i < 4; ++i) {
                    int ch = tid + 128 * i;
                    int row = ch >> 3, cc = ch & 7;
                    const float* g = src + bh64 + ((s0 + ST + row) << 9) + cc * 8;
                    float4 a = *(const float4*)g;
                    float4 c = *(const float4*)(g + 4);
                    uint4 pk;
                    pk.x = packh2(a.x, a.y); pk.y = packh2(a.z, a.w);
                    pk.z = packh2(c.x, c.y); pk.w = packh2(c.z, c.w);
                    *(uint4*)(dst + row * SH + cc * 8) = pk;
                }
            }
        }

        /* ---- QK^T: m16 x n64 x k64 ---- */
        float c[8][4];
        #pragma unroll
        for (int nb = 0; nb < 8; ++nb)
            #pragma unroll
            for (int q = 0; q < 4; ++q) c[nb][q] = 0.f;

        #pragma unroll
        for (int kb = 0; kb < 4; ++kb) {
            #pragma unroll
            for (int j = 0; j < 4; ++j) {
                int row = 16 * j + (g8 & 1) * 8 + rl;
                int col = kb * 16 + (g8 >> 1) * 8;
                uint32_t r0, r1, r2, r3;
                ldsm4(r0, r1, r2, r3, smem_u32(sK + row * SH + col));
                mma16(c[2 * j],     qa[kb], r0, r2);
                mma16(c[2 * j + 1], qa[kb], r1, r3);
            }
        }

        /* ---- diag replace + causal mask: only the last (diagonal) tile ---- */
        if (t == ntiles - 1) {
            #pragma unroll
            for (int st = 0; st < 2; ++st) {
                int lr = w * 16 + st * 8 + gid;
                int l = l0 + lr;
                float ds = sdiag[lr];
                #pragma unroll
                for (int nb = 0; nb < 8; ++nb)
                    #pragma unroll
                    for (int cc = 0; cc < 2; ++cc) {
                        int sg = s0 + nb * 8 + 2 * tig + cc;
                        float v = c[nb][2 * st + cc];
                        if (sg == l && l >= hist) v = ds;
                        if (sg > l) v = -1e30f;
                        c[nb][2 * st + cc] = v;
                    }
            }
        }

        /* ---- fused fp16 softmax + P·V + ones-column row sums ---- */
        #pragma unroll
        for (int kb = 0; kb < 4; ++kb) {
            uint32_t pa[4];
            pa[0] = hex2(hmul2u(packh2(c[2 * kb][0],     c[2 * kb][1]),     c2x2));
            pa[1] = hex2(hmul2u(packh2(c[2 * kb][2],     c[2 * kb][3]),     c2x2));
            pa[2] = hex2(hmul2u(packh2(c[2 * kb + 1][0], c[2 * kb + 1][1]), c2x2));
            pa[3] = hex2(hmul2u(packh2(c[2 * kb + 1][2], c[2 * kb + 1][3]), c2x2));
            int srow = kb * 16 + (g8 & 1) * 8 + rl;
            #pragma unroll
            for (int j = 0; j < 4; ++j) {
                int dcol = 16 * j + (g8 >> 1) * 8;
                uint32_t r0, r1, r2, r3;
                ldsm4t(r0, r1, r2, r3, smem_u32(sV + srow * SH + dcol));
                mma16(acc[2 * j],     pa, r0, r1);
                mma16(acc[2 * j + 1], pa, r2, r3);
            }
            mma16(acc[8], pa, ONE2, ONE2);
        }
        __syncthreads();
    }

    // ---- epilogue: normalize, delta correction ----
    #pragma unroll
    for (int st = 0; st < 2; ++st) {
        int lr = w * 16 + st * 8 + gid;
        int l = l0 + lr;
        float inv = 1.f / acc[8][2 * st];
        bool tail = (l >= hist);
        float pd = 0.f;
        if (tail) pd = ex2f(sdiag[lr] * C2) * inv;
        #pragma unroll
        for (int nb = 0; nb < 8; ++nb) {
            int d = nb * 8 + 2 * tig;
            int base = bh64 + (l << 9) + d;
            float o0 = acc[nb][2 * st] * inv;
            float o1 = acc[nb][2 * st + 1] * inv;
            if (tail) {
                float2 v2  = *(const float2*)(V  + base);
                float2 vd2 = *(const float2*)(VD + base);
                o0 += pd * (vd2.x - v2.x);
                o1 += pd * (vd2.y - v2.y);
            }
            *(float2*)(O + base) = make_float2(o0, o1);
        }
    }
}

extern "C" void kernel_launch(void* const* d_in, const int* in_sizes, int n_in,
                              void* d_out, int out_size) {
    const float* Q  = (const float*)d_in[0];
    const float* K  = (const float*)d_in[1];
    const float* V  = (const float*)d_in[2];
    const float* QD = (const float*)d_in[3];
    const float* KD = (const float*)d_in[4];
    const float* VD = (const float*)d_in[5];
    const int* histp = (const int*)d_in[(n_in >= 8) ? 7 : (n_in - 1)];

    size_t smem_bytes = (size_t)(QT * SH + 4 * ST * SH) * sizeof(__half) + QT * sizeof(float);
    cudaFuncSetAttribute(fftcca_h16v8,
                         cudaFuncAttributeMaxDynamicSharedMemorySize, (int)smem_bytes);

    dim3 grid(Lc / QT, Hc, Bc);
    fftcca_h16v8<<<grid, 128, smem_bytes>>>(Q, K, V, QD, KD, VD, histp, (float*)d_out);
}

// round 14
// speedup vs baseline: 1.1117x; 1.1117x over previous
#include <cuda_runtime.h>
#include <cuda_fp16.h>
#include <cstdint>

#define Bc 8
#define Lc 1024
#define Hc 8
#define Ec 64
#define QT 128     /* 4 warps x m32 rows */
#define ST 64
#define SH 72      /* smem row stride in halves */
#define C2 0.18033688f   /* 0.125 * log2(e) */
#define ONE2 0x3C003C00u /* half2(1.0, 1.0) */

__device__ __forceinline__ uint32_t smem_u32(const void* p) {
    return (uint32_t)__cvta_generic_to_shared(p);
}
__device__ __forceinline__ float ex2f(float x) {
    float r; asm("ex2.approx.f32 %0, %1;" : "=f"(r) : "f"(x)); return r;
}
__device__ __forceinline__ uint32_t hex2(uint32_t x) {
    uint32_t r; asm("ex2.approx.f16x2 %0, %1;" : "=r"(r) : "r"(x)); return r;
}
__device__ __forceinline__ uint32_t hmul2u(uint32_t a, uint32_t b) {
    uint32_t r; asm("mul.f16x2 %0, %1, %2;" : "=r"(r) : "r"(a), "r"(b)); return r;
}
__device__ __forceinline__ void ldsm4(uint32_t& r0, uint32_t& r1, uint32_t& r2, uint32_t& r3, uint32_t a) {
    asm volatile("ldmatrix.sync.aligned.m8n8.x4.shared.b16 {%0,%1,%2,%3}, [%4];"
        : "=r"(r0), "=r"(r1), "=r"(r2), "=r"(r3) : "r"(a));
}
__device__ __forceinline__ void ldsm4t(uint32_t& r0, uint32_t& r1, uint32_t& r2, uint32_t& r3, uint32_t a) {
    asm volatile("ldmatrix.sync.aligned.m8n8.x4.trans.shared.b16 {%0,%1,%2,%3}, [%4];"
        : "=r"(r0), "=r"(r1), "=r"(r2), "=r"(r3) : "r"(a));
}
__device__ __forceinline__ void mma16(float* d, const uint32_t* a, uint32_t b0, uint32_t b1) {
    asm volatile("mma.sync.aligned.m16n8k16.row.col.f32.f16.f16.f32 "
        "{%0,%1,%2,%3}, {%4,%5,%6,%7}, {%8,%9}, {%0,%1,%2,%3};"
        : "+f"(d[0]), "+f"(d[1]), "+f"(d[2]), "+f"(d[3])
        : "r"(a[0]), "r"(a[1]), "r"(a[2]), "r"(a[3]), "r"(b0), "r"(b1));
}
__device__ __forceinline__ uint32_t packh2(float x, float y) {
    __half2 h = __floats2half2_rn(x, y);
    return *(uint32_t*)&h;
}

__global__ __launch_bounds__(128, 2) void fftcca_h16v9(
    const float* __restrict__ Q, const float* __restrict__ K,
    const float* __restrict__ V, const float* __restrict__ QD,
    const float* __restrict__ KD, const float* __restrict__ VD,
    const int* __restrict__ histp, float* __restrict__ O)
{
    extern __shared__ __align__(16) char smraw[];
    __half* sq  = (__half*)smraw;                 // [128][72] q_eff
    __half* sKV = sq + QT * SH;                   // [2 stages][K|V][64][72]
    float* sdiag = (float*)(sKV + 4 * ST * SH);   // [128]

    const int hist = __ldg(histp);
    const int b = blockIdx.z, h = blockIdx.y;
    const int jt = (int)(gridDim.x - 1u - blockIdx.x);   // longest tiles first
    const int l0 = jt * QT;
    const int tid = threadIdx.x;
    const int w = tid >> 5, lane = tid & 31, gid = lane >> 2, tig = lane & 3;
    const int g8 = lane >> 3, rl = lane & 7;
    const uint32_t c2x2 = packh2(C2, C2);
    const int bh64 = ((b * Lc) * Hc + h) << 6;

    // ---- stage Q (row-select Q vs QD, cvt fp16): 2048 uint2, 128 threads ----
    #pragma unroll
    for (int i = 0; i < 16; ++i) {
        int gi = tid + 128 * i;
        int r = gi >> 4, c4 = (gi & 15) << 2;
        int l = l0 + r;
        const float* src = (l < hist) ? Q : QD;
        float4 v = *(const float4*)(src + bh64 + (l << 9) + c4);
        uint2 pk; pk.x = packh2(v.x, v.y); pk.y = packh2(v.z, v.w);
        *(uint2*)(sq + r * SH + c4) = pk;
    }

    // ---- raw diagonal scores (fp32 from global, 1 thread/row) ----
    {
        int l = l0 + tid;
        float s = 0.f;
        if (l >= hist) {
            int base = bh64 + (l << 9);
            #pragma unroll
            for (int e = 0; e < 64; e += 4) {
                float4 q4 = *(const float4*)(QD + base + e);
                float4 k4 = *(const float4*)(KD + base + e);
                s += q4.x * k4.x + q4.y * k4.y + q4.z * k4.z + q4.w * k4.w;
            }
        }
        sdiag[tid] = s;
    }
    __syncthreads();

    // ---- preload Q A-fragments for both m16 blocks (tile-invariant) ----
    uint32_t qa[2][4][4];
    #pragma unroll
    for (int mb = 0; mb < 2; ++mb)
        #pragma unroll
        for (int kb = 0; kb < 4; ++kb) {
            int row = w * 32 + mb * 16 + (g8 & 1) * 8 + rl;
            int col = kb * 16 + (g8 >> 1) * 8;
            ldsm4(qa[mb][kb][0], qa[mb][kb][1], qa[mb][kb][2], qa[mb][kb][3],
                  smem_u32(sq + row * SH + col));
        }

    /* acc[mb][0..7]: output dims; acc[mb][8]: ones-column row sums */
    float acc[2][9][4];
    #pragma unroll
    for (int mb = 0; mb < 2; ++mb)
        #pragma unroll
        for (int nb = 0; nb < 9; ++nb)
            #pragma unroll
            for (int q = 0; q < 4; ++q) acc[mb][nb][q] = 0.f;

    const int rowmax = l0 + w * 32 + 31;
    const int dtile = (l0 + w * 32) & ~63;   /* warp's 32 rows sit in one 64-block */
    const int ntiles = 2 * jt + 2;

    // ---- stage tile 0 into buffer 0: 512 chunks of 16B per array ----
    #pragma unroll
    for (int arr = 0; arr < 2; ++arr) {
        const float* src = arr ? V : K;
        __half* dst = sKV + arr * (ST * SH);
        #pragma unroll
        for (int i = 0; i < 4; ++i) {
            int ch = tid + 128 * i;
            int row = ch >> 3, cc = ch & 7;
            const float* g = src + bh64 + (row << 9) + cc * 8;
            float4 a = *(const float4*)g;
            float4 c = *(const float4*)(g + 4);
            uint4 pk;
            pk.x = packh2(a.x, a.y); pk.y = packh2(a.z, a.w);
            pk.z = packh2(c.x, c.y); pk.w = packh2(c.z, c.w);
            *(uint4*)(dst + row * SH + cc * 8) = pk;
        }
    }
    __syncthreads();

    for (int t = 0; t < ntiles; ++t) {
        const int s0 = t * ST;
        const int cur = t & 1;
        const __half* sK = sKV + cur * (2 * ST * SH);
        const __half* sV = sK + ST * SH;

        // ---- stage tile t+1 into the other buffer ----
        if (t + 1 < ntiles) {
            __half* dB = sKV + (cur ^ 1) * (2 * ST * SH);
            #pragma unroll
            for (int arr = 0; arr < 2; ++arr) {
                const float* src = arr ? V : K;
                __half* dst = dB + arr * (ST * SH);
                #pragma unroll
                for (int i = 0; i < 4; ++i) {
                    int ch = tid + 128 * i;
                    int row = ch >> 3, cc = ch & 7;
                    const float* g = src + bh64 + ((s0 + ST + row) << 9) + cc * 8;
                    float4 a = *(const float4*)g;
                    float4 c = *(const float4*)(g + 4);
                    uint4 pk;
                    pk.x = packh2(a.x, a.y); pk.y = packh2(a.z, a.w);
                    pk.z = packh2(c.x, c.y); pk.w = packh2(c.z, c.w);
                    *(uint4*)(dst + row * SH + cc * 8) = pk;
                }
            }
        }

        if (s0 <= rowmax) {
            /* ---- QK^T: m32 x n64 x k64, K-fragment shared across both m16 ---- */
            float c[2][8][4];
            #pragma unroll
            for (int mb = 0; mb < 2; ++mb)
                #pragma unroll
                for (int nb = 0; nb < 8; ++nb)
                    #pragma unroll
                    for (int q = 0; q < 4; ++q) c[mb][nb][q] = 0.f;

            #pragma unroll
            for (int kb = 0; kb < 4; ++kb) {
                #pragma unroll
                for (int j = 0; j < 4; ++j) {
                    int row = 16 * j + (g8 & 1) * 8 + rl;
                    int col = kb * 16 + (g8 >> 1) * 8;
                    uint32_t r0, r1, r2, r3;
                    ldsm4(r0, r1, r2, r3, smem_u32(sK + row * SH + col));
                    mma16(c[0][2 * j],     qa[0][kb], r0, r2);
                    mma16(c[0][2 * j + 1], qa[0][kb], r1, r3);
                    mma16(c[1][2 * j],     qa[1][kb], r0, r2);
                    mma16(c[1][2 * j + 1], qa[1][kb], r1, r3);
                }
            }

            /* ---- diag replace + causal mask (diagonal tile only) ---- */
            if (s0 == dtile) {
                #pragma unroll
                for (int mb = 0; mb < 2; ++mb)
                    #pragma unroll
                    for (int st = 0; st < 2; ++st) {
                        int lr = w * 32 + mb * 16 + st * 8 + gid;
                        int l = l0 + lr;
                        float ds = sdiag[lr];
                        #pragma unroll
                        for (int nb = 0; nb < 8; ++nb)
                            #pragma unroll
                            for (int cc = 0; cc < 2; ++cc) {
                                int sg = s0 + nb * 8 + 2 * tig + cc;
                                float v = c[mb][nb][2 * st + cc];
                                if (sg == l && l >= hist) v = ds;
                                if (sg > l) v = -1e30f;
                                c[mb][nb][2 * st + cc] = v;
                            }
                    }
            }

            /* ---- fused fp16 softmax + P·V, V-fragment shared across both m16 ---- */
            #pragma unroll
            for (int kb = 0; kb < 4; ++kb) {
                uint32_t pa[2][4];
                #pragma unroll
                for (int mb = 0; mb < 2; ++mb) {
                    pa[mb][0] = hex2(hmul2u(packh2(c[mb][2 * kb][0],     c[mb][2 * kb][1]),     c2x2));
                    pa[mb][1] = hex2(hmul2u(packh2(c[mb][2 * kb][2],     c[mb][2 * kb][3]),     c2x2));
                    pa[mb][2] = hex2(hmul2u(packh2(c[mb][2 * kb + 1][0], c[mb][2 * kb + 1][1]), c2x2));
                    pa[mb][3] = hex2(hmul2u(packh2(c[mb][2 * kb + 1][2], c[mb][2 * kb + 1][3]), c2x2));
                }
                int srow = kb * 16 + (g8 & 1) * 8 + rl;
                #pragma unroll
                for (int j = 0; j < 4; ++j) {
                    int dcol = 16 * j + (g8 >> 1) * 8;
                    uint32_t r0, r1, r2, r3;
                    ldsm4t(r0, r1, r2, r3, smem_u32(sV + srow * SH + dcol));
                    mma16(acc[0][2 * j],     pa[0], r0, r1);
                    mma16(acc[0][2 * j + 1], pa[0], r2, r3);
                    mma16(acc[1][2 * j],     pa[1], r0, r1);
                    mma16(acc[1][2 * j + 1], pa[1], r2, r3);
                }
                mma16(acc[0][8], pa[0], ONE2, ONE2);
                mma16(acc[1][8], pa[1], ONE2, ONE2);
            }
        }
        __syncthreads();
    }

    // ---- epilogue: normalize, delta correction ----
    #pragma unroll
    for (int mb = 0; mb < 2; ++mb)
        #pragma unroll
        for (int st = 0; st < 2; ++st) {
            int lr = w * 32 + mb * 16 + st * 8 + gid;
            int l = l0 + lr;
            float inv = 1.f / acc[mb][8][2 * st];
            bool tail = (l >= hist);
            float pd = 0.f;
            if (tail) pd = ex2f(sdiag[lr] * C2) * inv;
            #pragma unroll
            for (int nb = 0; nb < 8; ++nb) {
                int d = nb * 8 + 2 * tig;
                int base = bh64 + (l << 9) + d;
                float o0 = acc[mb][nb][2 * st] * inv;
                float o1 = acc[mb][nb][2 * st + 1] * inv;
                if (tail) {
                    float2 v2  = *(const float2*)(V  + base);
                    float2 vd2 = *(const float2*)(VD + base);
                    o0 += pd * (vd2.x - v2.x);
                    o1 += pd * (vd2.y - v2.y);
                }
                *(float2*)(O + base) = make_float2(o0, o1);
            }
        }
}

extern "C" void kernel_launch(void* const* d_in, const int* in_sizes, int n_in,
                              void* d_out, int out_size) {
    const float* Q  = (const float*)d_in[0];
    const float* K  = (const float*)d_in[1];
    const float* V  = (const float*)d_in[2];
    const float* QD = (const float*)d_in[3];
    const float* KD = (const float*)d_in[4];
    const float* VD = (const float*)d_in[5];
    const int* histp = (const int*)d_in[(n_in >= 8) ? 7 : (n_in - 1)];

    size_t smem_bytes = (size_t)(QT * SH + 4 * ST * SH) * sizeof(__half) + QT * sizeof(float);
    cudaFuncSetAttribute(fftcca_h16v9,
                         cudaFuncAttributeMaxDynamicSharedMemorySize, (int)smem_bytes);

    dim3 grid(Lc / QT, Hc, Bc);
    fftcca_h16v9<<<grid, 128, smem_bytes>>>(Q, K, V, QD, KD, VD, histp, (float*)d_out);
}

// round 16
// speedup vs baseline: 1.1209x; 1.0083x over previous
#include <cuda_runtime.h>
#include <cuda_fp16.h>
#include <cstdint>

#define Bc 8
#define Lc 1024
#define Hc 8
#define Ec 64
#define QT 128     /* 4 warps x m32 rows */
#define ST 128     /* two 64-col halves per barrier window */
#define SH 72      /* smem row stride in halves */
#define C2 0.18033688f   /* 0.125 * log2(e) */
#define ONE2 0x3C003C00u /* half2(1.0, 1.0) */

__device__ __forceinline__ uint32_t smem_u32(const void* p) {
    return (uint32_t)__cvta_generic_to_shared(p);
}
__device__ __forceinline__ float ex2f(float x) {
    float r; asm("ex2.approx.f32 %0, %1;" : "=f"(r) : "f"(x)); return r;
}
__device__ __forceinline__ uint32_t hex2(uint32_t x) {
    uint32_t r; asm("ex2.approx.f16x2 %0, %1;" : "=r"(r) : "r"(x)); return r;
}
__device__ __forceinline__ void ldsm4(uint32_t& r0, uint32_t& r1, uint32_t& r2, uint32_t& r3, uint32_t a) {
    asm volatile("ldmatrix.sync.aligned.m8n8.x4.shared.b16 {%0,%1,%2,%3}, [%4];"
        : "=r"(r0), "=r"(r1), "=r"(r2), "=r"(r3) : "r"(a));
}
__device__ __forceinline__ void ldsm4t(uint32_t& r0, uint32_t& r1, uint32_t& r2, uint32_t& r3, uint32_t a) {
    asm volatile("ldmatrix.sync.aligned.m8n8.x4.trans.shared.b16 {%0,%1,%2,%3}, [%4];"
        : "=r"(r0), "=r"(r1), "=r"(r2), "=r"(r3) : "r"(a));
}
__device__ __forceinline__ void mma16(float* d, const uint32_t* a, uint32_t b0, uint32_t b1) {
    asm volatile("mma.sync.aligned.m16n8k16.row.col.f32.f16.f16.f32 "
        "{%0,%1,%2,%3}, {%4,%5,%6,%7}, {%8,%9}, {%0,%1,%2,%3};"
        : "+f"(d[0]), "+f"(d[1]), "+f"(d[2]), "+f"(d[3])
        : "r"(a[0]), "r"(a[1]), "r"(a[2]), "r"(a[3]), "r"(b0), "r"(b1));
}
__device__ __forceinline__ uint32_t packh2(float x, float y) {
    __half2 h = __floats2half2_rn(x, y);
    return *(uint32_t*)&h;
}

__global__ __launch_bounds__(128, 2) void fftcca_h16v10(
    const float* __restrict__ Q, const float* __restrict__ K,
    const float* __restrict__ V, const float* __restrict__ QD,
    const float* __restrict__ KD, const float* __restrict__ VD,
    const int* __restrict__ histp, float* __restrict__ O)
{
    extern __shared__ __align__(16) char smraw[];
    __half* sq  = (__half*)smraw;                 // [128][72] q_eff * C2
    __half* sKV = sq + QT * SH;                   // [2 stages][K 128 | V 128][72]
    float* sdiag = (float*)(sKV + 2 * 2 * ST * SH); // [128]

    const int hist = __ldg(histp);
    const int b = blockIdx.z, h = blockIdx.y;
    const int jt = (int)(gridDim.x - 1u - blockIdx.x);   // longest tiles first
    const int l0 = jt * QT;
    const int tid = threadIdx.x;
    const int w = tid >> 5, lane = tid & 31, gid = lane >> 2, tig = lane & 3;
    const int g8 = lane >> 3, rl = lane & 7;
    const int bh64 = ((b * Lc) * Hc + h) << 6;

    // ---- stage Q scaled by C2 (row-select Q vs QD, cvt fp16) ----
    #pragma unroll
    for (int i = 0; i < 16; ++i) {
        int gi = tid + 128 * i;
        int r = gi >> 4, c4 = (gi & 15) << 2;
        int l = l0 + r;
        const float* src = (l < hist) ? Q : QD;
        float4 v = *(const float4*)(src + bh64 + (l << 9) + c4);
        uint2 pk;
        pk.x = packh2(v.x * C2, v.y * C2);
        pk.y = packh2(v.z * C2, v.w * C2);
        *(uint2*)(sq + r * SH + c4) = pk;
    }

    // ---- raw diagonal scores (fp32 from global, 1 thread/row) ----
    {
        int l = l0 + tid;
        float s = 0.f;
        if (l >= hist) {
            int base = bh64 + (l << 9);
            #pragma unroll
            for (int e = 0; e < 64; e += 4) {
                float4 q4 = *(const float4*)(QD + base + e);
                float4 k4 = *(const float4*)(KD + base + e);
                s += q4.x * k4.x + q4.y * k4.y + q4.z * k4.z + q4.w * k4.w;
            }
        }
        sdiag[tid] = s;
    }
    __syncthreads();

    // ---- preload Q A-fragments for both m16 blocks (tile-invariant) ----
    uint32_t qa[2][4][4];
    #pragma unroll
    for (int mb = 0; mb < 2; ++mb)
        #pragma unroll
        for (int kb = 0; kb < 4; ++kb) {
            int row = w * 32 + mb * 16 + (g8 & 1) * 8 + rl;
            int col = kb * 16 + (g8 >> 1) * 8;
            ldsm4(qa[mb][kb][0], qa[mb][kb][1], qa[mb][kb][2], qa[mb][kb][3],
                  smem_u32(sq + row * SH + col));
        }

    /* acc[mb][0..7]: output dims; acc[mb][8]: ones-column row sums */
    float acc[2][9][4];
    #pragma unroll
    for (int mb = 0; mb < 2; ++mb)
        #pragma unroll
        for (int nb = 0; nb < 9; ++nb)
            #pragma unroll
            for (int q = 0; q < 4; ++q) acc[mb][nb][q] = 0.f;

    const int rowmax = l0 + w * 32 + 31;
    const int dtile = (l0 + w * 32) & ~63;
    const int ntiles = jt + 1;

    // ---- stage tile 0 into buffer 0: 1024 chunks of 16B per array ----
    #pragma unroll
    for (int arr = 0; arr < 2; ++arr) {
        const float* src = arr ? V : K;
        __half* dst = sKV + arr * (ST * SH);
        #pragma unroll
        for (int i = 0; i < 8; ++i) {
            int ch = tid + 128 * i;
            int row = ch >> 3, cc = ch & 7;
            const float* g = src + bh64 + (row << 9) + cc * 8;
            float4 a = *(const float4*)g;
            float4 c = *(const float4*)(g + 4);
            uint4 pk;
            pk.x = packh2(a.x, a.y); pk.y = packh2(a.z, a.w);
            pk.z = packh2(c.x, c.y); pk.w = packh2(c.z, c.w);
            *(uint4*)(dst + row * SH + cc * 8) = pk;
        }
    }
    __syncthreads();

    for (int t = 0; t < ntiles; ++t) {
        const int s0 = t * ST;
        const int cur = t & 1;
        const __half* sK = sKV + cur * (2 * ST * SH);
        const __half* sV = sK + ST * SH;

        // ---- stage tile t+1 into the other buffer ----
        if (t + 1 < ntiles) {
            __half* dB = sKV + (cur ^ 1) * (2 * ST * SH);
            #pragma unroll
            for (int arr = 0; arr < 2; ++arr) {
                const float* src = arr ? V : K;
                __half* dst = dB + arr * (ST * SH);
                #pragma unroll
                for (int i = 0; i < 8; ++i) {
                    int ch = tid + 128 * i;
                    int row = ch >> 3, cc = ch & 7;
                    const float* g = src + bh64 + ((s0 + ST + row) << 9) + cc * 8;
                    float4 a = *(const float4*)g;
                    float4 c = *(const float4*)(g + 4);
                    uint4 pk;
                    pk.x = packh2(a.x, a.y); pk.y = packh2(a.z, a.w);
                    pk.z = packh2(c.x, c.y); pk.w = packh2(c.z, c.w);
                    *(uint4*)(dst + row * SH + cc * 8) = pk;
                }
            }
        }

        /* ---- two 64-col halves per barrier window ---- */
        #pragma unroll
        for (int hf = 0; hf < 2; ++hf) {
            const int sb = s0 + hf * 64;
            if (sb > rowmax) continue;
            const __half* sKh = sK + hf * 64 * SH;
            const __half* sVh = sV + hf * 64 * SH;

            /* ---- QK^T: m32 x n64 x k64 (scores pre-scaled via Q) ---- */
            float c[2][8][4];
            #pragma unroll
            for (int mb = 0; mb < 2; ++mb)
                #pragma unroll
                for (int nb = 0; nb < 8; ++nb)
                    #pragma unroll
                    for (int q = 0; q < 4; ++q) c[mb][nb][q] = 0.f;

            #pragma unroll
            for (int kb = 0; kb < 4; ++kb) {
                #pragma unroll
                for (int j = 0; j < 4; ++j) {
                    int row = 16 * j + (g8 & 1) * 8 + rl;
                    int col = kb * 16 + (g8 >> 1) * 8;
                    uint32_t r0, r1, r2, r3;
                    ldsm4(r0, r1, r2, r3, smem_u32(sKh + row * SH + col));
                    mma16(c[0][2 * j],     qa[0][kb], r0, r2);
                    mma16(c[0][2 * j + 1], qa[0][kb], r1, r3);
                    mma16(c[1][2 * j],     qa[1][kb], r0, r2);
                    mma16(c[1][2 * j + 1], qa[1][kb], r1, r3);
                }
            }

            /* ---- diag replace + causal mask (diagonal half only) ---- */
            if (sb == dtile) {
                #pragma unroll
                for (int mb = 0; mb < 2; ++mb)
                    #pragma unroll
                    for (int st = 0; st < 2; ++st) {
                        int lr = w * 32 + mb * 16 + st * 8 + gid;
                        int l = l0 + lr;
                        float ds = sdiag[lr] * C2;   /* scaled domain */
                        #pragma unroll
                        for (int nb = 0; nb < 8; ++nb)
                            #pragma unroll
                            for (int cc = 0; cc < 2; ++cc) {
                                int sg = sb + nb * 8 + 2 * tig + cc;
                                float v = c[mb][nb][2 * st + cc];
                                if (sg == l && l >= hist) v = ds;
                                if (sg > l) v = -1e30f;
                                c[mb][nb][2 * st + cc] = v;
                            }
                    }
            }

            /* ---- softmax (pack -> ex2 only) + P·V + ones-column sums ---- */
            #pragma unroll
            for (int kb = 0; kb < 4; ++kb) {
                uint32_t pa[2][4];
                #pragma unroll
                for (int mb = 0; mb < 2; ++mb) {
                    pa[mb][0] = hex2(packh2(c[mb][2 * kb][0],     c[mb][2 * kb][1]));
                    pa[mb][1] = hex2(packh2(c[mb][2 * kb][2],     c[mb][2 * kb][3]));
                    pa[mb][2] = hex2(packh2(c[mb][2 * kb + 1][0], c[mb][2 * kb + 1][1]));
                    pa[mb][3] = hex2(packh2(c[mb][2 * kb + 1][2], c[mb][2 * kb + 1][3]));
                }
                int srow = kb * 16 + (g8 & 1) * 8 + rl;
                #pragma unroll
                for (int j = 0; j < 4; ++j) {
                    int dcol = 16 * j + (g8 >> 1) * 8;
                    uint32_t r0, r1, r2, r3;
                    ldsm4t(r0, r1, r2, r3, smem_u32(sVh + srow * SH + dcol));
                    mma16(acc[0][2 * j],     pa[0], r0, r1);
                    mma16(acc[0][2 * j + 1], pa[0], r2, r3);
                    mma16(acc[1][2 * j],     pa[1], r0, r1);
                    mma16(acc[1][2 * j + 1], pa[1], r2, r3);
                }
                mma16(acc[0][8], pa[0], ONE2, ONE2);
                mma16(acc[1][8], pa[1], ONE2, ONE2);
            }
        }
        __syncthreads();
    }

    // ---- epilogue: normalize, delta correction ----
    #pragma unroll
    for (int mb = 0; mb < 2; ++mb)
        #pragma unroll
        for (int st = 0; st < 2; ++st) {
            int lr = w * 32 + mb * 16 + st * 8 + gid;
            int l = l0 + lr;
            float inv = 1.f / acc[mb][8][2 * st];
            bool tail = (l >= hist);
            float pd = 0.f;
            if (tail) pd = ex2f(sdiag[lr] * C2) * inv;
            #pragma unroll
            for (int nb = 0; nb < 8; ++nb) {
                int d = nb * 8 + 2 * tig;
                int base = bh64 + (l << 9) + d;
                float o0 = acc[mb][nb][2 * st] * inv;
                float o1 = acc[mb][nb][2 * st + 1] * inv;
                if (tail) {
                    float2 v2  = *(const float2*)(V  + base);
                    float2 vd2 = *(const float2*)(VD + base);
                    o0 += pd * (vd2.x - v2.x);
                    o1 += pd * (vd2.y - v2.y);
                }
                *(float2*)(O + base) = make_float2(o0, o1);
            }
        }
}

extern "C" void kernel_launch(void* const* d_in, const int* in_sizes, int n_in,
                              void* d_out, int out_size) {
    const float* Q  = (const float*)d_in[0];
    const float* K  = (const float*)d_in[1];
    const float* V  = (const float*)d_in[2];
    const float* QD = (const float*)d_in[3];
    const float* KD = (const float*)d_in[4];
    const float* VD = (const float*)d_in[5];
    const int* histp = (const int*)d_in[(n_in >= 8) ? 7 : (n_in - 1)];

    size_t smem_bytes = (size_t)(QT * SH + 4 * ST * SH) * sizeof(__half) + QT * sizeof(float);
    cudaFuncSetAttribute(fftcca_h16v10,
                         cudaFuncAttributeMaxDynamicSharedMemorySize, (int)smem_bytes);

    dim3 grid(Lc / QT, Hc, Bc);
    fftcca_h16v10<<<grid, 128, smem_bytes>>>(Q, K, V, QD, KD, VD, histp, (float*)d_out);
}